// round 2
// baseline (speedup 1.0000x reference)
#include <cuda_runtime.h>

// ---------------- problem constants ----------------
#define NB      4096
#define NNOTES  48
#define NF      256
#define NU      256
#define NG      1024      // 4 * NU (i,f,g,o)
#define IN0     259       // NF + 3
#define MROWS   32        // batch rows per CTA
#define NTHR    512
#define KC      8         // K rows staged per chunk
#define XSTRIDE 260       // padded x row stride (multiple of 4)

typedef unsigned long long u64;

// ---------------- device scratch (static, allocation-guard-safe) ----------------
__device__ __align__(16) float g_Wt_ih0[IN0 * NG];
__device__ __align__(16) float g_Wt_hh0[NU * NG];
__device__ __align__(16) float g_Wt_ih1[NU * NG];
__device__ __align__(16) float g_Wt_hh1[NU * NG];
__device__ __align__(16) float g_b0[NG];
__device__ __align__(16) float g_b1[NG];

// ---------------- helpers ----------------
__device__ __forceinline__ u64 pack2(float x) {
    u64 r;
    asm("mov.b64 %0, {%1, %1};" : "=l"(r) : "r"(__float_as_uint(x)));
    return r;
}
__device__ __forceinline__ void fma2(u64& acc, u64 a, u64 b) {
    // packed 2x fp32 FMA (sm_100+): acc = a*b + acc, per 32-bit lane
    asm("fma.rn.f32x2 %0, %1, %2, %0;" : "+l"(acc) : "l"(a), "l"(b));
}
__device__ __forceinline__ void unpack2(u64 v, float& lo, float& hi) {
    unsigned int a, b;
    asm("mov.b64 {%0, %1}, %2;" : "=r"(a), "=r"(b) : "l"(v));
    lo = __uint_as_float(a);
    hi = __uint_as_float(b);
}
__device__ __forceinline__ float sigf(float x) {
    return 1.0f / (1.0f + expf(-x));
}

// ---------------- prep: transpose weights, combine biases ----------------
__global__ void prep_kernel(const float* __restrict__ W_ih0, const float* __restrict__ W_hh0,
                            const float* __restrict__ b_ih0, const float* __restrict__ b_hh0,
                            const float* __restrict__ W_ih1, const float* __restrict__ W_hh1,
                            const float* __restrict__ b_ih1, const float* __restrict__ b_hh1) {
    int tid = blockIdx.x * blockDim.x + threadIdx.x;
    int stride = gridDim.x * blockDim.x;
    for (int i = tid; i < IN0 * NG; i += stride) {
        int k = i / NG, j = i - k * NG;
        g_Wt_ih0[i] = W_ih0[j * IN0 + k];
    }
    for (int i = tid; i < NU * NG; i += stride) {
        int k = i / NG, j = i - k * NG;
        g_Wt_hh0[i] = W_hh0[j * NU + k];
        g_Wt_ih1[i] = W_ih1[j * NU + k];
        g_Wt_hh1[i] = W_hh1[j * NU + k];
    }
    for (int i = tid; i < NG; i += stride) {
        g_b0[i] = b_ih0[i] + b_hh0[i];
        g_b1[i] = b_ih1[i] + b_hh1[i];
    }
}

// ---------------- GEMM accumulate: acc[4 rows][4 gates][2 pairs] ----------------
// Thread (rg, ug) owns rows rg*4..rg*4+3 and hidden columns
// {2ug, 2ug+1, 128+2ug, 128+2ug+1} of each gate block.
__device__ __forceinline__ void gemm_accum(
    u64 (&acc)[4][4][2],
    const float* Arow,          // base of this thread's first row (shared mem)
    int astride,
    const float* __restrict__ Wg,  // transposed weights [ktot][NG] in global
    int ktot,
    float* sh_w, int ug, int tid)
{
    for (int k0 = 0; k0 < ktot; k0 += KC) {
        int kc = ktot - k0;
        if (kc > KC) kc = KC;
        __syncthreads();
        {
            int nf4 = kc * (NG / 4);
            const float4* src = (const float4*)(Wg + (size_t)k0 * NG);
            float4* dst = (float4*)sh_w;
            for (int i = tid; i < nf4; i += NTHR) dst[i] = src[i];
        }
        __syncthreads();
        const float* wbase = sh_w + 2 * ug;
#pragma unroll
        for (int kk = 0; kk < KC; kk++) {
            if (kk < kc) {
                u64 a[4];
#pragma unroll
                for (int r = 0; r < 4; r++) a[r] = pack2(Arow[r * astride + k0 + kk]);
                const float* wr = wbase + kk * NG;
#pragma unroll
                for (int g = 0; g < 4; g++) {
#pragma unroll
                    for (int p = 0; p < 2; p++) {
                        u64 w = *(const u64*)(wr + g * 256 + p * 128);
#pragma unroll
                        for (int r = 0; r < 4; r++) fma2(acc[r][g][p], a[r], w);
                    }
                }
            }
        }
    }
}

// ---------------- LSTM cell elementwise ----------------
__device__ __forceinline__ void cell_update(
    u64 (&acc)[4][4][2], float* shc, float* shh, int rg, int ug)
{
    float hnew[4][2][2];
#pragma unroll
    for (int r = 0; r < 4; r++) {
        int row = rg * 4 + r;
#pragma unroll
        for (int p = 0; p < 2; p++) {
            float iv0, iv1, fv0, fv1, gv0, gv1, ov0, ov1;
            unpack2(acc[r][0][p], iv0, iv1);
            unpack2(acc[r][1][p], fv0, fv1);
            unpack2(acc[r][2][p], gv0, gv1);
            unpack2(acc[r][3][p], ov0, ov1);
            int u0 = p * 128 + 2 * ug;
            float c0 = shc[row * NU + u0];
            float c1 = shc[row * NU + u0 + 1];
            float cn0 = sigf(fv0) * c0 + sigf(iv0) * tanhf(gv0);
            float cn1 = sigf(fv1) * c1 + sigf(iv1) * tanhf(gv1);
            shc[row * NU + u0]     = cn0;   // c is thread-exclusive: no sync needed
            shc[row * NU + u0 + 1] = cn1;
            hnew[r][p][0] = sigf(ov0) * tanhf(cn0);
            hnew[r][p][1] = sigf(ov1) * tanhf(cn1);
        }
    }
    __syncthreads();   // all GEMM readers of old h are done
#pragma unroll
    for (int r = 0; r < 4; r++) {
        int row = rg * 4 + r;
#pragma unroll
        for (int p = 0; p < 2; p++) {
            int u0 = p * 128 + 2 * ug;
            shh[row * NU + u0]     = hnew[r][p][0];
            shh[row * NU + u0 + 1] = hnew[r][p][1];
        }
    }
    __syncthreads();
}

// ---------------- main persistent kernel ----------------
__global__ void __launch_bounds__(NTHR, 1)
noteaxis_kernel(const float* __restrict__ feats,
                const float* __restrict__ cond,
                const float* __restrict__ Wout,
                const float* __restrict__ bout,
                float* __restrict__ out)
{
    extern __shared__ float smem[];
    float* sh_w  = smem;                        // KC*NG      = 8192 floats
    float* sh_x  = sh_w + KC * NG;              // 32*260     = 8320 floats
    float* sh_h0 = sh_x + MROWS * XSTRIDE;      // 8192
    float* sh_h1 = sh_h0 + MROWS * NU;          // 8192
    float* sh_c0 = sh_h1 + MROWS * NU;          // 8192
    float* sh_c1 = sh_c0 + MROWS * NU;          // 8192

    int tid = threadIdx.x;
    int rg = tid >> 6;         // 0..7 -> rows rg*4 .. rg*4+3
    int ug = tid & 63;         // hidden pair base = 2*ug
    int row0 = rg * 4;
    size_t batch0 = (size_t)blockIdx.x * MROWS;

    for (int i = tid; i < MROWS * NU; i += NTHR) {
        sh_h0[i] = 0.f; sh_h1[i] = 0.f; sh_c0[i] = 0.f; sh_c1[i] = 0.f;
    }

    for (int n = 0; n < NNOTES; n++) {
        __syncthreads();
        // ---- load x tile: [32 rows][259] = features ++ shifted cond notes ----
        for (int i = tid; i < MROWS * (NF / 4); i += NTHR) {
            int r = i >> 6;
            int c = i & 63;
            float4 v = ((const float4*)(feats + ((batch0 + r) * NNOTES + n) * NF))[c];
            ((float4*)(sh_x + r * XSTRIDE))[c] = v;
        }
        if (tid < MROWS * 3) {
            int r = tid / 3, c = tid - r * 3;
            sh_x[r * XSTRIDE + NF + c] =
                (n == 0) ? 0.f : cond[((batch0 + r) * NNOTES + (n - 1)) * 3 + c];
        }
        // (gemm_accum's leading barrier orders these writes before reads)

        u64 acc[4][4][2];

        // ---- layer 0 ----
#pragma unroll
        for (int g = 0; g < 4; g++) {
#pragma unroll
            for (int p = 0; p < 2; p++) {
                u64 bv = *(const u64*)(g_b0 + g * 256 + p * 128 + 2 * ug);
#pragma unroll
                for (int r = 0; r < 4; r++) acc[r][g][p] = bv;
            }
        }
        gemm_accum(acc, sh_x + row0 * XSTRIDE, XSTRIDE, g_Wt_ih0, IN0, sh_w, ug, tid);
        gemm_accum(acc, sh_h0 + row0 * NU,     NU,      g_Wt_hh0, NU,  sh_w, ug, tid);
        cell_update(acc, sh_c0, sh_h0, rg, ug);

        // ---- layer 1 ----
#pragma unroll
        for (int g = 0; g < 4; g++) {
#pragma unroll
            for (int p = 0; p < 2; p++) {
                u64 bv = *(const u64*)(g_b1 + g * 256 + p * 128 + 2 * ug);
#pragma unroll
                for (int r = 0; r < 4; r++) acc[r][g][p] = bv;
            }
        }
        gemm_accum(acc, sh_h0 + row0 * NU, NU, g_Wt_ih1, NU, sh_w, ug, tid);
        gemm_accum(acc, sh_h1 + row0 * NU, NU, g_Wt_hh1, NU, sh_w, ug, tid);
        cell_update(acc, sh_c1, sh_h1, rg, ug);

        // ---- output head: out[b,n,ch] = sigmoid?(h1 . Wout[ch] + bout[ch]) ----
        if (tid < MROWS * 3) {
            int r = tid / 3, ch = tid - r * 3;
            const float4* hv = (const float4*)(sh_h1 + r * NU);
            const float4* wv = (const float4*)(Wout + ch * NU);
            float s = bout[ch];
#pragma unroll 8
            for (int q = 0; q < NU / 4; q++) {
                float4 h4 = hv[q];
                float4 w4 = wv[q];
                s += h4.x * w4.x + h4.y * w4.y + h4.z * w4.z + h4.w * w4.w;
            }
            if (ch < 2) s = sigf(s);
            out[((batch0 + r) * NNOTES + n) * 3 + ch] = s;
        }
        // top-of-loop barrier protects sh_x / sh_w reuse and sh_h1 readers
    }
}

// ---------------- launch ----------------
extern "C" void kernel_launch(void* const* d_in, const int* in_sizes, int n_in,
                              void* d_out, int out_size)
{
    const float* feats = (const float*)d_in[0];
    const float* cond  = (const float*)d_in[1];
    const float* W_ih0 = (const float*)d_in[2];
    const float* W_hh0 = (const float*)d_in[3];
    const float* b_ih0 = (const float*)d_in[4];
    const float* b_hh0 = (const float*)d_in[5];
    const float* W_ih1 = (const float*)d_in[6];
    const float* W_hh1 = (const float*)d_in[7];
    const float* b_ih1 = (const float*)d_in[8];
    const float* b_hh1 = (const float*)d_in[9];
    const float* W_out = (const float*)d_in[10];
    const float* b_out = (const float*)d_in[11];
    float* out = (float*)d_out;

    prep_kernel<<<264, 256>>>(W_ih0, W_hh0, b_ih0, b_hh0, W_ih1, W_hh1, b_ih1, b_hh1);

    int smem_bytes = (KC * NG + MROWS * XSTRIDE + 4 * MROWS * NU) * (int)sizeof(float);
    cudaFuncSetAttribute(noteaxis_kernel,
                         cudaFuncAttributeMaxDynamicSharedMemorySize, smem_bytes);
    noteaxis_kernel<<<NB / MROWS, NTHR, smem_bytes>>>(feats, cond, W_out, b_out, out);
}